// round 12
// baseline (speedup 1.0000x reference)
#include <cuda_runtime.h>
#include <cuda_fp16.h>
#include <cstdint>

// Problem constants (fixed by the reference)
#define NC   1024      // n_concepts (K)
#define NL   512       // n_lemmas   (N)
#define BTOT 4096      // batch      (M)
#define TSTEPS 50
#define GAMMA_C 0.95f
#define KAPPA_C 0.1f
#define FLOOR_C 1e-6f
#define A_SCALE   512.0f     // exact pow2; A pre-scaled into fp16 range
#define LO_SCALE  2048.0f    // exact pow2; lo planes scaled to fp16-normal range

// ---------------- device scratch (no runtime alloc allowed) ----------------
__device__ __align__(1024) float  g_drive[(size_t)BTOT * NL];   // 8 MB (holds 512*drive)
__device__ __align__(1024) __half g_Ah[2][BTOT][NC];            // 16 MB (hi, lo*2048)
__device__ __align__(1024) __half g_Wh[2][NL][NC];              // 2 MB  (hi, lo*2048)

// ---------------------------- PTX helpers (base ISA only) -------------------
__device__ __forceinline__ uint32_t smem_u32(const void* p) {
    uint32_t a;
    asm("{ .reg .u64 t; cvta.to.shared.u64 t, %1; cvt.u32.u64 %0, t; }" : "=r"(a) : "l"(p));
    return a;
}
__device__ __forceinline__ void cp16(uint32_t dst, const void* src) {
    asm volatile("cp.async.cg.shared.global [%0], [%1], 16;" :: "r"(dst), "l"(src));
}
#define CP_COMMIT() asm volatile("cp.async.commit_group;" ::: "memory")
#define CP_WAIT2()  asm volatile("cp.async.wait_group 2;" ::: "memory")

#define LDSM4(r, addr) \
    asm volatile("ldmatrix.sync.aligned.m8n8.x4.shared.b16 {%0,%1,%2,%3}, [%4];" \
        : "=r"((r)[0]), "=r"((r)[1]), "=r"((r)[2]), "=r"((r)[3]) : "r"(addr))

// fp32-accumulator fp16 MMA (hi*hi term)
#define MMAF32(d, a, b0, b1) \
    asm volatile("mma.sync.aligned.m16n8k16.row.col.f32.f16.f16.f32 " \
        "{%0,%1,%2,%3}, {%4,%5,%6,%7}, {%8,%9}, {%0,%1,%2,%3};" \
        : "+f"((d)[0]), "+f"((d)[1]), "+f"((d)[2]), "+f"((d)[3]) \
        : "r"((a)[0]), "r"((a)[1]), "r"((a)[2]), "r"((a)[3]), "r"(b0), "r"(b1))

// fp16-accumulator fp16 MMA (correction terms, 2x rate)
#define MMAF16(d, a, b0, b1) \
    asm volatile("mma.sync.aligned.m16n8k16.row.col.f16.f16.f16.f16 " \
        "{%0,%1}, {%2,%3,%4,%5}, {%6,%7}, {%0,%1};" \
        : "+r"((d)[0]), "+r"((d)[1]) \
        : "r"((a)[0]), "r"((a)[1]), "r"((a)[2]), "r"((a)[3]), "r"(b0), "r"(b1))

// ------------------- fp32 -> fp16 hi + scaled-lo split ----------------------
__device__ __forceinline__ void split8(const float* src, __half* dhi, __half* dlo,
                                       float scale) {
    float4 v0 = reinterpret_cast<const float4*>(src)[0];
    float4 v1 = reinterpret_cast<const float4*>(src)[1];
    float f[8] = {v0.x * scale, v0.y * scale, v0.z * scale, v0.w * scale,
                  v1.x * scale, v1.y * scale, v1.z * scale, v1.w * scale};
    __half h[8]; __half l[8];
    #pragma unroll
    for (int i = 0; i < 8; i++) {
        h[i] = __float2half_rn(f[i]);
        l[i] = __float2half_rn((f[i] - __half2float(h[i])) * LO_SCALE);
    }
    *reinterpret_cast<uint4*>(dhi) = *reinterpret_cast<uint4*>(h);
    *reinterpret_cast<uint4*>(dlo) = *reinterpret_cast<uint4*>(l);
}

__global__ __launch_bounds__(256) void convert_kernel(
    const float* __restrict__ A, const float* __restrict__ W, int nA, int nW)
{
    int i = (blockIdx.x * blockDim.x + threadIdx.x) * 8;
    if (i < nA) {
        split8(A + i, &g_Ah[0][0][0] + i, &g_Ah[1][0][0] + i, A_SCALE);
    } else {
        int j = i - nA;
        if (j >= nW) return;
        split8(W + j, &g_Wh[0][0][0] + j, &g_Wh[1][0][0] + j, 1.0f);
    }
}

// ------------------------- HMMA GEMM ----------------------------------------
// 512*drive = Ahi@Whi^T  (fp32 accum)
//           + [Ahi@Wlo^T + Alo@Whi^T] / 2048   (shared fp16 accum, 2x rate)
// 3 K-segments of 16 K64 chunks each; seg0 -> fp32 accum, seg1/2 -> fp16.
// CTA 128x128, 8 warps (4M x 2N), warp tile 32x64. 4-stage cp.async pipeline,
// fragment double-buffering. Rows padded to 144 B (9*16, coprime 8).
#define ROW_B   144
#define TILE_B  (128 * ROW_B)          // 18432 B
#define STAGE_B (2 * TILE_B)           // A + W tile
#define STG     4
#define SMEM_TOT (STG * STAGE_B)       // 147456 B

__global__ __launch_bounds__(256, 1) void gemm_hmma_kernel(
    const __half* __restrict__ Ahi, const __half* __restrict__ Alo,
    const __half* __restrict__ Whi, const __half* __restrict__ Wlo,
    float* __restrict__ D)
{
    extern __shared__ __align__(128) char smem[];
    const uint32_t sb = smem_u32(smem);
    const int tid = threadIdx.x, lane = tid & 31, wid = tid >> 5;
    const int wm = wid & 3, wn = wid >> 2;          // 4 x 2 warp grid
    const int m0 = blockIdx.y * 128, n0 = blockIdx.x * 128;

    float acc[2][8][4];
    uint32_t acch[2][8][2];                          // fp16x2 accum (corrections)
    #pragma unroll
    for (int a = 0; a < 2; a++)
        #pragma unroll
        for (int b = 0; b < 8; b++) {
            #pragma unroll
            for (int c = 0; c < 4; c++) acc[a][b][c] = 0.f;
            acch[a][b][0] = 0u; acch[a][b][1] = 0u;
        }

    // Load K64 chunk for global iteration it: seg picks plane pair.
    auto load_chunk = [&](int it, int s) {
        const int seg = it >> 4;
        const int k0  = (it & 15) << 6;
        const __half* Ap = (seg == 2) ? Alo : Ahi;
        const __half* Wp = (seg == 1) ? Wlo : Whi;
        const uint32_t da = sb + s * STAGE_B;
        const uint32_t db = da + TILE_B;
        #pragma unroll
        for (int i = 0; i < 4; i++) {
            const int ci = i * 256 + tid;
            const int r = ci >> 3, cc = ci & 7;
            const uint32_t ro = r * ROW_B + cc * 16;
            cp16(da + ro, Ap + (size_t)(m0 + r) * NC + k0 + cc * 8);
            cp16(db + ro, Wp + (size_t)(n0 + r) * NC + k0 + cc * 8);
        }
        CP_COMMIT();
    };

    load_chunk(0, 0); load_chunk(1, 1); load_chunk(2, 2);

    uint32_t ar[2][2][4], br[2][4][4];
    auto ldfrag = [&](uint32_t aB, uint32_t bB, int kk, int f) {
        const uint32_t kb = kk * 32 + ((lane >> 4) << 4);
        #pragma unroll
        for (int mi = 0; mi < 2; mi++) {
            const uint32_t ro = (wm * 32 + mi * 16 + (lane & 15)) * ROW_B + kb;
            LDSM4(ar[f][mi], aB + ro);
        }
        #pragma unroll
        for (int ni = 0; ni < 4; ni++) {
            const uint32_t ro = (wn * 64 + ni * 16 + (lane & 15)) * ROW_B + kb;
            LDSM4(br[f][ni], bB + ro);
        }
    };

    const int NIT = 48;                              // 3 segs x 16 chunks
    for (int it = 0; it < NIT; ++it) {
        const int s = it & 3;
        const bool hi_seg = (it < 16);
        CP_WAIT2();
        __syncthreads();
        if (it + 3 < NIT) load_chunk(it + 3, (it + 3) & 3);
        else CP_COMMIT();                            // keep group count uniform

        const uint32_t aB = sb + s * STAGE_B;
        const uint32_t bB = aB + TILE_B;

        ldfrag(aB, bB, 0, 0);
        #pragma unroll
        for (int kk = 0; kk < 4; ++kk) {
            const int cur = kk & 1;
            if (kk < 3) ldfrag(aB, bB, kk + 1, cur ^ 1);
            if (hi_seg) {
                #pragma unroll
                for (int mi = 0; mi < 2; mi++)
                    #pragma unroll
                    for (int ni = 0; ni < 4; ni++) {
                        MMAF32(acc[mi][ni * 2],     ar[cur][mi], br[cur][ni][0], br[cur][ni][2]);
                        MMAF32(acc[mi][ni * 2 + 1], ar[cur][mi], br[cur][ni][1], br[cur][ni][3]);
                    }
            } else {
                #pragma unroll
                for (int mi = 0; mi < 2; mi++)
                    #pragma unroll
                    for (int ni = 0; ni < 4; ni++) {
                        MMAF16(acch[mi][ni * 2],     ar[cur][mi], br[cur][ni][0], br[cur][ni][2]);
                        MMAF16(acch[mi][ni * 2 + 1], ar[cur][mi], br[cur][ni][1], br[cur][ni][3]);
                    }
            }
        }
    }

    // ---- epilogue: combine fp32 hi + fp16 corrections, write scaled drive ----
    const float inv_lo = 1.0f / LO_SCALE;
    #pragma unroll
    for (int mi = 0; mi < 2; mi++) {
        const int row = m0 + wm * 32 + mi * 16 + (lane >> 2);
        #pragma unroll
        for (int nj = 0; nj < 8; nj++) {
            const int col = n0 + wn * 64 + nj * 8 + (lane & 3) * 2;
            const __half2 c0 = *reinterpret_cast<const __half2*>(&acch[mi][nj][0]);
            const __half2 c1 = *reinterpret_cast<const __half2*>(&acch[mi][nj][1]);
            float2 w0 = make_float2(fmaf(__low2float(c0),  inv_lo, acc[mi][nj][0]),
                                    fmaf(__high2float(c0), inv_lo, acc[mi][nj][1]));
            float2 w1 = make_float2(fmaf(__low2float(c1),  inv_lo, acc[mi][nj][2]),
                                    fmaf(__high2float(c1), inv_lo, acc[mi][nj][3]));
            *reinterpret_cast<float2*>(&D[(size_t)row * NL + col]) = w0;
            *reinterpret_cast<float2*>(&D[(size_t)(row + 8) * NL + col]) = w1;
        }
    }
}

// ---------------------------------------------------------------------------
// Recurrence + selection: TWO rows per warp (ILP on shfl chains), tree-sum.
// dv carries the 1/512 unscale of the drive.
// ---------------------------------------------------------------------------
__device__ __forceinline__ float tree_sum16(const float* a) {
    float t[8];
    #pragma unroll
    for (int j = 0; j < 8; j++) t[j] = a[j] + a[j + 8];
    #pragma unroll
    for (int j = 0; j < 4; j++) t[j] += t[j + 4];
    t[0] += t[2]; t[1] += t[3];
    return t[0] + t[1];
}

__global__ __launch_bounds__(256) void iterate_kernel(
    const float* __restrict__ D, const float* __restrict__ a0,
    float* __restrict__ out, int B, int write_aux)
{
    const int warp0 = (((blockIdx.x * blockDim.x + threadIdx.x) >> 5) << 1);
    const int lane = threadIdx.x & 31;
    if (warp0 >= B) return;

    const float inv_s = 1.0f / A_SCALE;
    float dv[2][16], a[2][16];
    #pragma unroll
    for (int r = 0; r < 2; r++) {
        const size_t ro = (size_t)(warp0 + r) * NL;
        #pragma unroll
        for (int i = 0; i < 16; i++) {
            dv[r][i] = D [ro + lane + 32 * i] * inv_s;
            a[r][i]  = a0[ro + lane + 32 * i];
        }
    }

    const float c1 = 1.0f + KAPPA_C;
    #pragma unroll 1
    for (int t = 0; t < TSTEPS; t++) {
        #pragma unroll
        for (int r = 0; r < 2; r++)
            #pragma unroll
            for (int i = 0; i < 16; i++)
                a[r][i] = fmaf(GAMMA_C, a[r][i], dv[r][i]);
        float p0 = tree_sum16(a[0]);
        float p1 = tree_sum16(a[1]);
        #pragma unroll
        for (int o = 16; o; o >>= 1) {
            p0 += __shfl_xor_sync(0xffffffffu, p0, o);
            p1 += __shfl_xor_sync(0xffffffffu, p1, o);
        }
        const float k0 = -KAPPA_C * p0, k1 = -KAPPA_C * p1;
        #pragma unroll
        for (int i = 0; i < 16; i++) {
            a[0][i] = fmaxf(fmaf(c1, a[0][i], k0), 0.f);
            a[1][i] = fmaxf(fmaf(c1, a[1][i], k1), 0.f);
        }
    }

    #pragma unroll
    for (int r = 0; r < 2; r++) {
        float s = 0.f, m = -1.f;
        int mi = NL;
        #pragma unroll
        for (int i = 0; i < 16; i++) {
            float v = a[r][i];
            s += v;
            if (v > m) { m = v; mi = lane + 32 * i; }
        }
        #pragma unroll
        for (int o = 16; o; o >>= 1) {
            float om  = __shfl_xor_sync(0xffffffffu, m,  o);
            int   omi = __shfl_xor_sync(0xffffffffu, mi, o);
            float os  = __shfl_xor_sync(0xffffffffu, s,  o);
            s += os;
            if (om > m || (om == m && omi < mi)) { m = om; mi = omi; }
        }
        const size_t ro = (size_t)(warp0 + r) * NL;
        #pragma unroll
        for (int i = 0; i < 16; i++)
            out[ro + lane + 32 * i] = a[r][i];
        if (lane == 0 && write_aux) {
            const size_t base = (size_t)B * NL;
            out[base + warp0 + r]     = (float)mi;
            out[base + B + warp0 + r] = m / fmaxf(s * (1.0f / NL), FLOOR_C);
        }
    }
}

// ---------------------------------------------------------------------------
extern "C" void kernel_launch(void* const* d_in, const int* in_sizes, int n_in,
                              void* d_out, int out_size)
{
    const float* c_lex = (const float*)d_in[0];   // (B, 1024)
    const float* W     = (const float*)d_in[1];   // (512, 1024)
    const float* a0    = (const float*)d_in[2];   // (B, 512)
    float* out = (float*)d_out;

    const int B = in_sizes[0] / NC;               // 4096

    float* drive = nullptr;
    void*  ah = nullptr;
    void*  wh = nullptr;
    cudaGetSymbolAddress((void**)&drive, g_drive);
    cudaGetSymbolAddress(&ah, g_Ah);
    cudaGetSymbolAddress(&wh, g_Wh);
    const __half* Ahi = (const __half*)ah;
    const __half* Alo = Ahi + (size_t)BTOT * NC;
    const __half* Whi = (const __half*)wh;
    const __half* Wlo = Whi + (size_t)NL * NC;

    // ---- phase 0: fp32 -> fp16 hi + scaled-lo planes ----
    const int nA = B * NC, nW = NL * NC;
    const int nthr8 = (nA + nW) / 8;
    convert_kernel<<<(nthr8 + 255) / 256, 256>>>(c_lex, W, nA, nW);

    // ---- phase 1: scaled drive via fp16 HMMA (fp32 hi + fp16 corrections) --
    cudaFuncSetAttribute(gemm_hmma_kernel,
                         cudaFuncAttributeMaxDynamicSharedMemorySize, SMEM_TOT);
    dim3 ggrid(NL / 128, B / 128);   // (4, 32) = 128 CTAs, one wave
    gemm_hmma_kernel<<<ggrid, 256, SMEM_TOT>>>(Ahi, Alo, Whi, Wlo, drive);

    // ---- phase 2: 50-step recurrence + selection (2 rows/warp) ----
    const int write_aux = (out_size >= B * NL + 2 * B) ? 1 : 0;
    const int nwarp = B / 2;                       // 2048 warps
    const int nblk = (nwarp * 32 + 255) / 256;     // 256 blocks
    iterate_kernel<<<nblk, 256>>>(drive, a0, out, B, write_aux);
}

// round 14
// speedup vs baseline: 1.1611x; 1.1611x over previous
#include <cuda_runtime.h>
#include <cuda_fp16.h>
#include <cstdint>

// Problem constants (fixed by the reference)
#define NC   1024      // n_concepts (K)
#define NL   512       // n_lemmas   (N)
#define BTOT 4096      // batch      (M)
#define TSTEPS 50
#define GAMMA_C 0.95f
#define KAPPA_C 0.1f
#define FLOOR_C 1e-6f
#define A_SCALE   512.0f     // exact pow2; A pre-scaled into fp16 range
#define LO_SCALE  2048.0f    // exact pow2; lo planes scaled past fp16 subnormals

// ---------------- device scratch (no runtime alloc allowed) ----------------
__device__ __align__(1024) float  g_drive[(size_t)BTOT * NL];   // 8 MB (512*drive)
__device__ __align__(1024) __half g_Ah[2][BTOT][NC];            // 16 MB (hi, lo*2048)
__device__ __align__(1024) __half g_Wh[2][NL][NC];              // 2 MB  (hi, lo*2048)

// ---------------------------- PTX helpers (base ISA only) -------------------
__device__ __forceinline__ uint32_t smem_u32(const void* p) {
    uint32_t a;
    asm("{ .reg .u64 t; cvta.to.shared.u64 t, %1; cvt.u32.u64 %0, t; }" : "=r"(a) : "l"(p));
    return a;
}
__device__ __forceinline__ void cp16(uint32_t dst, const void* src) {
    asm volatile("cp.async.cg.shared.global [%0], [%1], 16;" :: "r"(dst), "l"(src));
}
#define CP_COMMIT() asm volatile("cp.async.commit_group;" ::: "memory")
#define CP_WAIT1()  asm volatile("cp.async.wait_group 1;" ::: "memory")

#define LDSM4(r, addr) \
    asm volatile("ldmatrix.sync.aligned.m8n8.x4.shared.b16 {%0,%1,%2,%3}, [%4];" \
        : "=r"((r)[0]), "=r"((r)[1]), "=r"((r)[2]), "=r"((r)[3]) : "r"(addr))

#define MMAF32(d, a, b0, b1) \
    asm volatile("mma.sync.aligned.m16n8k16.row.col.f32.f16.f16.f32 " \
        "{%0,%1,%2,%3}, {%4,%5,%6,%7}, {%8,%9}, {%0,%1,%2,%3};" \
        : "+f"((d)[0]), "+f"((d)[1]), "+f"((d)[2]), "+f"((d)[3]) \
        : "r"((a)[0]), "r"((a)[1]), "r"((a)[2]), "r"((a)[3]), "r"(b0), "r"(b1))

// ------------------- fp32 -> fp16 hi + scaled-lo split ----------------------
__device__ __forceinline__ void split8(const float* src, __half* dhi, __half* dlo,
                                       float scale) {
    float4 v0 = reinterpret_cast<const float4*>(src)[0];
    float4 v1 = reinterpret_cast<const float4*>(src)[1];
    float f[8] = {v0.x * scale, v0.y * scale, v0.z * scale, v0.w * scale,
                  v1.x * scale, v1.y * scale, v1.z * scale, v1.w * scale};
    __half h[8]; __half l[8];
    #pragma unroll
    for (int i = 0; i < 8; i++) {
        h[i] = __float2half_rn(f[i]);
        l[i] = __float2half_rn((f[i] - __half2float(h[i])) * LO_SCALE);
    }
    *reinterpret_cast<uint4*>(dhi) = *reinterpret_cast<uint4*>(h);
    *reinterpret_cast<uint4*>(dlo) = *reinterpret_cast<uint4*>(l);
}

__global__ __launch_bounds__(256) void convert_kernel(
    const float* __restrict__ A, const float* __restrict__ W, int nA, int nW)
{
    int i = (blockIdx.x * blockDim.x + threadIdx.x) * 8;
    if (i < nA) {
        split8(A + i, &g_Ah[0][0][0] + i, &g_Ah[1][0][0] + i, A_SCALE);
    } else {
        int j = i - nA;
        if (j >= nW) return;
        split8(W + j, &g_Wh[0][0][0] + j, &g_Wh[1][0][0] + j, 1.0f);
    }
}

// ------------------------- HMMA GEMM (R8 structure, fp16 planes) ------------
// 512*drive = Ahi@Whi^T + [Ahi@Wlo^T + Alo@Whi^T]/2048, all terms fused per
// K64 chunk (Ahi/Whi fragments reused across terms). fp32 accum everywhere:
// acc1 for hi*hi, acc2 (shared) for the two 2048-scaled correction terms.
// CTA 128x128, 8 warps (4M x 2N), 3-stage cp.async pipeline.
// Rows padded to 144 B (9*16, coprime 8 -> conflict-free ldmatrix).
#define ROW_B   144
#define TILE_B  (128 * ROW_B)          // 18432 B
#define STAGE_B (4 * TILE_B)           // Ahi, Alo, Whi, Wlo
#define STG     3
#define SMEM_TOT (STG * STAGE_B)       // 221184 B

__global__ __launch_bounds__(256, 1) void gemm_hmma_kernel(
    const __half* __restrict__ Ahi, const __half* __restrict__ Alo,
    const __half* __restrict__ Whi, const __half* __restrict__ Wlo,
    float* __restrict__ D)
{
    extern __shared__ __align__(128) char smem[];
    const uint32_t sb = smem_u32(smem);
    const int tid = threadIdx.x, lane = tid & 31, wid = tid >> 5;
    const int wm = wid & 3, wn = wid >> 2;          // 4 x 2 warp grid
    const int m0 = blockIdx.y * 128, n0 = blockIdx.x * 128;

    float acc1[2][8][4], acc2[2][8][4];
    #pragma unroll
    for (int a = 0; a < 2; a++)
        #pragma unroll
        for (int b = 0; b < 8; b++)
            #pragma unroll
            for (int c = 0; c < 4; c++) { acc1[a][b][c] = 0.f; acc2[a][b][c] = 0.f; }

    // Load one K64 chunk: all 4 planes (4096 16B-chunks / 256 thr = 16 each).
    auto load_chunk = [&](int c, int s) {
        const int k0 = c << 6;
        const uint32_t st = sb + s * STAGE_B;
        const __half* srcs[4] = {
            Ahi + (size_t)m0 * NC + k0, Alo + (size_t)m0 * NC + k0,
            Whi + (size_t)n0 * NC + k0, Wlo + (size_t)n0 * NC + k0 };
        #pragma unroll
        for (int t = 0; t < 4; t++) {
            const uint32_t dst = st + t * TILE_B;
            const __half* src = srcs[t];
            #pragma unroll
            for (int i = 0; i < 4; i++) {
                const int ci = i * 256 + tid;
                const int r = ci >> 3, cc = ci & 7;
                cp16(dst + r * ROW_B + cc * 16, src + (size_t)r * NC + cc * 8);
            }
        }
        CP_COMMIT();
    };

    load_chunk(0, 0);
    load_chunk(1, 1);

    const int NCHUNK = NC / 64;                      // 16
    for (int c = 0; c < NCHUNK; ++c) {
        const int s = c % 3;
        CP_WAIT1();
        __syncthreads();
        if (c + 2 < NCHUNK) load_chunk(c + 2, (c + 2) % 3);
        else CP_COMMIT();

        const uint32_t aHi = sb + s * STAGE_B;
        const uint32_t aLo = aHi + TILE_B;
        const uint32_t bHi = aHi + 2 * TILE_B;
        const uint32_t bLo = aHi + 3 * TILE_B;

        #pragma unroll
        for (int kk = 0; kk < 4; ++kk) {
            const uint32_t kb = kk * 32 + ((lane >> 4) << 4);
            uint32_t arh[2][4], arl[2][4], brh[4][4], brl[4][4];
            #pragma unroll
            for (int mi = 0; mi < 2; mi++) {
                const uint32_t ro = (wm * 32 + mi * 16 + (lane & 15)) * ROW_B + kb;
                LDSM4(arh[mi], aHi + ro);
                LDSM4(arl[mi], aLo + ro);
            }
            #pragma unroll
            for (int ni = 0; ni < 4; ni++) {
                const uint32_t ro = (wn * 64 + ni * 16 + (lane & 15)) * ROW_B + kb;
                LDSM4(brh[ni], bHi + ro);
                LDSM4(brl[ni], bLo + ro);
            }
            #pragma unroll
            for (int mi = 0; mi < 2; mi++)
                #pragma unroll
                for (int ni = 0; ni < 4; ni++) {
                    MMAF32(acc1[mi][ni * 2],     arh[mi], brh[ni][0], brh[ni][2]);
                    MMAF32(acc1[mi][ni * 2 + 1], arh[mi], brh[ni][1], brh[ni][3]);
                    MMAF32(acc2[mi][ni * 2],     arh[mi], brl[ni][0], brl[ni][2]);
                    MMAF32(acc2[mi][ni * 2 + 1], arh[mi], brl[ni][1], brl[ni][3]);
                    MMAF32(acc2[mi][ni * 2],     arl[mi], brh[ni][0], brh[ni][2]);
                    MMAF32(acc2[mi][ni * 2 + 1], arl[mi], brh[ni][1], brh[ni][3]);
                }
        }
    }

    // ---- epilogue: drive = acc1 + acc2/2048 (still 512-scaled) ----
    const float inv_lo = 1.0f / LO_SCALE;
    #pragma unroll
    for (int mi = 0; mi < 2; mi++) {
        const int row = m0 + wm * 32 + mi * 16 + (lane >> 2);
        #pragma unroll
        for (int nj = 0; nj < 8; nj++) {
            const int col = n0 + wn * 64 + nj * 8 + (lane & 3) * 2;
            *reinterpret_cast<float2*>(&D[(size_t)row * NL + col]) =
                make_float2(fmaf(acc2[mi][nj][0], inv_lo, acc1[mi][nj][0]),
                            fmaf(acc2[mi][nj][1], inv_lo, acc1[mi][nj][1]));
            *reinterpret_cast<float2*>(&D[(size_t)(row + 8) * NL + col]) =
                make_float2(fmaf(acc2[mi][nj][2], inv_lo, acc1[mi][nj][2]),
                            fmaf(acc2[mi][nj][3], inv_lo, acc1[mi][nj][3]));
        }
    }
}

// ---------------------------------------------------------------------------
// Recurrence + selection: FOUR rows per warp (4 independent shfl chains hide
// SHFL latency; issue-bound). dv carries the 1/512 unscale. ~160 regs.
// ---------------------------------------------------------------------------
__device__ __forceinline__ float tree_sum16(const float* a) {
    float t[8];
    #pragma unroll
    for (int j = 0; j < 8; j++) t[j] = a[j] + a[j + 8];
    #pragma unroll
    for (int j = 0; j < 4; j++) t[j] += t[j + 4];
    t[0] += t[2]; t[1] += t[3];
    return t[0] + t[1];
}

__global__ __launch_bounds__(128) void iterate_kernel(
    const float* __restrict__ D, const float* __restrict__ a0,
    float* __restrict__ out, int B, int write_aux)
{
    const int warp0 = (((blockIdx.x * blockDim.x + threadIdx.x) >> 5) << 2);
    const int lane = threadIdx.x & 31;
    if (warp0 >= B) return;

    const float inv_s = 1.0f / A_SCALE;
    float dv[4][16], a[4][16];
    #pragma unroll
    for (int r = 0; r < 4; r++) {
        const size_t ro = (size_t)(warp0 + r) * NL;
        #pragma unroll
        for (int i = 0; i < 16; i++) {
            dv[r][i] = D [ro + lane + 32 * i] * inv_s;
            a[r][i]  = a0[ro + lane + 32 * i];
        }
    }

    const float c1 = 1.0f + KAPPA_C;
    #pragma unroll 1
    for (int t = 0; t < TSTEPS; t++) {
        float p[4];
        #pragma unroll
        for (int r = 0; r < 4; r++) {
            #pragma unroll
            for (int i = 0; i < 16; i++)
                a[r][i] = fmaf(GAMMA_C, a[r][i], dv[r][i]);
            p[r] = tree_sum16(a[r]);
        }
        #pragma unroll
        for (int o = 16; o; o >>= 1) {
            #pragma unroll
            for (int r = 0; r < 4; r++)
                p[r] += __shfl_xor_sync(0xffffffffu, p[r], o);
        }
        #pragma unroll
        for (int r = 0; r < 4; r++) {
            const float kk = -KAPPA_C * p[r];
            #pragma unroll
            for (int i = 0; i < 16; i++)
                a[r][i] = fmaxf(fmaf(c1, a[r][i], kk), 0.f);
        }
    }

    #pragma unroll
    for (int r = 0; r < 4; r++) {
        float s = 0.f, m = -1.f;
        int mi = NL;
        #pragma unroll
        for (int i = 0; i < 16; i++) {
            float v = a[r][i];
            s += v;
            if (v > m) { m = v; mi = lane + 32 * i; }
        }
        #pragma unroll
        for (int o = 16; o; o >>= 1) {
            float om  = __shfl_xor_sync(0xffffffffu, m,  o);
            int   omi = __shfl_xor_sync(0xffffffffu, mi, o);
            float os  = __shfl_xor_sync(0xffffffffu, s,  o);
            s += os;
            if (om > m || (om == m && omi < mi)) { m = om; mi = omi; }
        }
        const size_t ro = (size_t)(warp0 + r) * NL;
        #pragma unroll
        for (int i = 0; i < 16; i++)
            out[ro + lane + 32 * i] = a[r][i];
        if (lane == 0 && write_aux) {
            const size_t base = (size_t)B * NL;
            out[base + warp0 + r]     = (float)mi;
            out[base + B + warp0 + r] = m / fmaxf(s * (1.0f / NL), FLOOR_C);
        }
    }
}

// ---------------------------------------------------------------------------
extern "C" void kernel_launch(void* const* d_in, const int* in_sizes, int n_in,
                              void* d_out, int out_size)
{
    const float* c_lex = (const float*)d_in[0];   // (B, 1024)
    const float* W     = (const float*)d_in[1];   // (512, 1024)
    const float* a0    = (const float*)d_in[2];   // (B, 512)
    float* out = (float*)d_out;

    const int B = in_sizes[0] / NC;               // 4096

    float* drive = nullptr;
    void*  ah = nullptr;
    void*  wh = nullptr;
    cudaGetSymbolAddress((void**)&drive, g_drive);
    cudaGetSymbolAddress(&ah, g_Ah);
    cudaGetSymbolAddress(&wh, g_Wh);
    const __half* Ahi = (const __half*)ah;
    const __half* Alo = Ahi + (size_t)BTOT * NC;
    const __half* Whi = (const __half*)wh;
    const __half* Wlo = Whi + (size_t)NL * NC;

    // ---- phase 0: fp32 -> fp16 hi + scaled-lo planes ----
    const int nA = B * NC, nW = NL * NC;
    const int nthr8 = (nA + nW) / 8;
    convert_kernel<<<(nthr8 + 255) / 256, 256>>>(c_lex, W, nA, nW);

    // ---- phase 1: scaled drive via fp16 HMMA, 3 terms fused per chunk ----
    cudaFuncSetAttribute(gemm_hmma_kernel,
                         cudaFuncAttributeMaxDynamicSharedMemorySize, SMEM_TOT);
    dim3 ggrid(NL / 128, B / 128);   // (4, 32) = 128 CTAs, one wave
    gemm_hmma_kernel<<<ggrid, 256, SMEM_TOT>>>(Ahi, Alo, Whi, Wlo, drive);

    // ---- phase 2: 50-step recurrence + selection (4 rows/warp) ----
    const int write_aux = (out_size >= B * NL + 2 * B) ? 1 : 0;
    const int nwarp = B / 4;                       // 1024 warps
    const int nblk = (nwarp * 32 + 127) / 128;     // 256 blocks of 128 thr
    iterate_kernel<<<nblk, 128>>>(drive, a0, out, B, write_aux);
}

// round 15
// speedup vs baseline: 1.1952x; 1.0294x over previous
#include <cuda_runtime.h>
#include <cuda_fp16.h>
#include <cstdint>

// Problem constants (fixed by the reference)
#define NC   1024      // n_concepts (K)
#define NL   512       // n_lemmas   (N)
#define BTOT 4096      // batch      (M)
#define TSTEPS 50
#define GAMMA_C 0.95f
#define KAPPA_C 0.1f
#define FLOOR_C 1e-6f
#define A_SCALE   512.0f     // exact pow2; A pre-scaled into fp16 range
#define LO_SCALE  2048.0f    // exact pow2; lo planes scaled past fp16 subnormals

// ---------------- device scratch (no runtime alloc allowed) ----------------
__device__ __align__(1024) float  g_drive[(size_t)BTOT * NL];   // 8 MB (512*drive)
__device__ __align__(1024) __half g_Wh[2][NL][NC];              // 2 MB  (hi, lo*2048)

// ---------------------------- PTX helpers (base ISA only) -------------------
__device__ __forceinline__ uint32_t smem_u32(const void* p) {
    uint32_t a;
    asm("{ .reg .u64 t; cvta.to.shared.u64 t, %1; cvt.u32.u64 %0, t; }" : "=r"(a) : "l"(p));
    return a;
}
__device__ __forceinline__ void cp16(uint32_t dst, const void* src) {
    asm volatile("cp.async.cg.shared.global [%0], [%1], 16;" :: "r"(dst), "l"(src));
}
#define CP_COMMIT() asm volatile("cp.async.commit_group;" ::: "memory")
#define CP_WAIT0()  asm volatile("cp.async.wait_group 0;" ::: "memory")
#define CP_WAIT1()  asm volatile("cp.async.wait_group 1;" ::: "memory")

#define LDSM4(r, addr) \
    asm volatile("ldmatrix.sync.aligned.m8n8.x4.shared.b16 {%0,%1,%2,%3}, [%4];" \
        : "=r"((r)[0]), "=r"((r)[1]), "=r"((r)[2]), "=r"((r)[3]) : "r"(addr))

#define MMAF32(d, a, b0, b1) \
    asm volatile("mma.sync.aligned.m16n8k16.row.col.f32.f16.f16.f32 " \
        "{%0,%1,%2,%3}, {%4,%5,%6,%7}, {%8,%9}, {%0,%1,%2,%3};" \
        : "+f"((d)[0]), "+f"((d)[1]), "+f"((d)[2]), "+f"((d)[3]) \
        : "r"((a)[0]), "r"((a)[1]), "r"((a)[2]), "r"((a)[3]), "r"(b0), "r"(b1))

// ------------------- fp32 -> fp16 hi + scaled-lo split ----------------------
__global__ __launch_bounds__(256) void convert_W_kernel(const float* __restrict__ W) {
    int i = (blockIdx.x * blockDim.x + threadIdx.x) * 8;
    if (i >= NL * NC) return;
    float4 v0 = reinterpret_cast<const float4*>(W + i)[0];
    float4 v1 = reinterpret_cast<const float4*>(W + i)[1];
    float f[8] = {v0.x, v0.y, v0.z, v0.w, v1.x, v1.y, v1.z, v1.w};
    __half h[8]; __half l[8];
    #pragma unroll
    for (int j = 0; j < 8; j++) {
        h[j] = __float2half_rn(f[j]);
        l[j] = __float2half_rn((f[j] - __half2float(h[j])) * LO_SCALE);
    }
    *reinterpret_cast<uint4*>(&g_Wh[0][0][0] + i) = *reinterpret_cast<uint4*>(h);
    *reinterpret_cast<uint4*>(&g_Wh[1][0][0] + i) = *reinterpret_cast<uint4*>(l);
}

// ------------------------- HMMA GEMM with fused A conversion ----------------
// 512*drive = Ahi@Whi^T + [Ahi@Wlo^T + Alo@Whi^T]/2048, 3 terms fused per K64
// chunk. A is loaded as RAW fp32 via LDG, split to fp16 hi/lo in-register, and
// STS'd into the next stage (no gmem round trip). W planes pre-converted, via
// cp.async. CTA 128x128, 8 warps (4M x 2N), 2-stage pipeline.
// Rows padded to 144 B (9*16, coprime 8 -> conflict-free ldmatrix).
#define ROW_B   144
#define TILE_B  (128 * ROW_B)          // 18432 B
#define STAGE_B (4 * TILE_B)           // Ahi, Alo, Whi, Wlo
#define STG     2
#define SMEM_TOT (STG * STAGE_B)       // 147456 B

__global__ __launch_bounds__(256, 1) void gemm_hmma_kernel(
    const float* __restrict__ Af32,
    const __half* __restrict__ Whi, const __half* __restrict__ Wlo,
    float* __restrict__ D)
{
    extern __shared__ __align__(128) char smem[];
    const uint32_t sb = smem_u32(smem);
    const int tid = threadIdx.x, lane = tid & 31, wid = tid >> 5;
    const int wm = wid & 3, wn = wid >> 2;          // 4 x 2 warp grid
    const int m0 = blockIdx.y * 128, n0 = blockIdx.x * 128;

    float acc1[2][8][4], acc2[2][8][4];
    #pragma unroll
    for (int a = 0; a < 2; a++)
        #pragma unroll
        for (int b = 0; b < 8; b++)
            #pragma unroll
            for (int c = 0; c < 4; c++) { acc1[a][b][c] = 0.f; acc2[a][b][c] = 0.f; }

    // W cp.async for one K64 chunk into stage s (2048 cp16 / 256 thr = 8 each)
    auto load_W = [&](int c, int s) {
        const int k0 = c << 6;
        const uint32_t wb = sb + s * STAGE_B + 2 * TILE_B;   // Whi then Wlo
        #pragma unroll
        for (int i = 0; i < 4; i++) {
            const int ci = i * 256 + tid;
            const int r = ci >> 3, cc = ci & 7;
            const uint32_t ro = r * ROW_B + cc * 16;
            cp16(wb + ro,          Whi + (size_t)(n0 + r) * NC + k0 + cc * 8);
            cp16(wb + TILE_B + ro, Wlo + (size_t)(n0 + r) * NC + k0 + cc * 8);
        }
        CP_COMMIT();
    };

    // A fp32 LDG batch (4 float4/thread) + convert + STS into stage s.
    // Chunk = 128 rows x 64 f32 = 2048 float4; batch b covers ci in
    // [b*1024, b*1024+1024): ci = b*1024 + i*256 + tid, r = ci>>4, c4 = ci&15.
    float4 v[4];
    auto ldg_A = [&](int c, int b) {
        const int k0 = c << 6;
        #pragma unroll
        for (int i = 0; i < 4; i++) {
            const int ci = b * 1024 + i * 256 + tid;
            const int r = ci >> 4, c4 = ci & 15;
            v[i] = *reinterpret_cast<const float4*>(
                Af32 + (size_t)(m0 + r) * NC + k0 + c4 * 4);
        }
    };
    auto cvt_sts_A = [&](int b, int s) {
        const uint32_t ab = sb + s * STAGE_B;                // Ahi then Alo
        #pragma unroll
        for (int i = 0; i < 4; i++) {
            const int ci = b * 1024 + i * 256 + tid;
            const int r = ci >> 4, c4 = ci & 15;
            float f[4] = {v[i].x * A_SCALE, v[i].y * A_SCALE,
                          v[i].z * A_SCALE, v[i].w * A_SCALE};
            __half h[4], l[4];
            #pragma unroll
            for (int j = 0; j < 4; j++) {
                h[j] = __float2half_rn(f[j]);
                l[j] = __float2half_rn((f[j] - __half2float(h[j])) * LO_SCALE);
            }
            const uint32_t ro = r * ROW_B + c4 * 8;
            *reinterpret_cast<uint2*>(smem + s * STAGE_B + ro) =
                *reinterpret_cast<uint2*>(h);
            *reinterpret_cast<uint2*>(smem + s * STAGE_B + TILE_B + ro) =
                *reinterpret_cast<uint2*>(l);
            (void)ab;
        }
    };

    auto mma_kk = [&](int s, int kk) {
        const uint32_t aHi = sb + s * STAGE_B;
        const uint32_t aLo = aHi + TILE_B;
        const uint32_t bHi = aHi + 2 * TILE_B;
        const uint32_t bLo = aHi + 3 * TILE_B;
        const uint32_t kb = kk * 32 + ((lane >> 4) << 4);
        uint32_t arh[2][4], arl[2][4], brh[4][4], brl[4][4];
        #pragma unroll
        for (int mi = 0; mi < 2; mi++) {
            const uint32_t ro = (wm * 32 + mi * 16 + (lane & 15)) * ROW_B + kb;
            LDSM4(arh[mi], aHi + ro);
            LDSM4(arl[mi], aLo + ro);
        }
        #pragma unroll
        for (int ni = 0; ni < 4; ni++) {
            const uint32_t ro = (wn * 64 + ni * 16 + (lane & 15)) * ROW_B + kb;
            LDSM4(brh[ni], bHi + ro);
            LDSM4(brl[ni], bLo + ro);
        }
        #pragma unroll
        for (int mi = 0; mi < 2; mi++)
            #pragma unroll
            for (int ni = 0; ni < 4; ni++) {
                MMAF32(acc1[mi][ni * 2],     arh[mi], brh[ni][0], brh[ni][2]);
                MMAF32(acc1[mi][ni * 2 + 1], arh[mi], brh[ni][1], brh[ni][3]);
                MMAF32(acc2[mi][ni * 2],     arh[mi], brl[ni][0], brl[ni][2]);
                MMAF32(acc2[mi][ni * 2 + 1], arh[mi], brl[ni][1], brl[ni][3]);
                MMAF32(acc2[mi][ni * 2],     arl[mi], brh[ni][0], brh[ni][2]);
                MMAF32(acc2[mi][ni * 2 + 1], arl[mi], brh[ni][1], brh[ni][3]);
            }
    };

    // ---- preamble: W(0)->s0, W(1)->s1 via cp.async; A(0) via LDG+STS ----
    load_W(0, 0);
    load_W(1, 1);
    ldg_A(0, 0); cvt_sts_A(0, 0);
    ldg_A(0, 1); cvt_sts_A(1, 0);
    CP_WAIT1();                      // W(0) landed (W(1) may be in flight)
    __syncthreads();                 // A(0) + W(0) visible to all

    const int NCHUNK = NC / 64;      // 16
    for (int c = 0; c < NCHUNK; ++c) {
        const int s = c & 1;
        if (c > 0) {
            CP_WAIT0();              // W(c) landed
            __syncthreads();         // A(c) visible; MMA(c-1) done with s
            if (c + 1 < NCHUNK) load_W(c + 1, s ^ 1);
        }
        if (c + 1 < NCHUNK) ldg_A(c + 1, 0);
        mma_kk(s, 0);
        mma_kk(s, 1);
        if (c + 1 < NCHUNK) { cvt_sts_A(0, s ^ 1); ldg_A(c + 1, 1); }
        mma_kk(s, 2);
        mma_kk(s, 3);
        if (c + 1 < NCHUNK) cvt_sts_A(1, s ^ 1);
    }

    // ---- epilogue: drive = acc1 + acc2/2048 (still 512-scaled) ----
    const float inv_lo = 1.0f / LO_SCALE;
    #pragma unroll
    for (int mi = 0; mi < 2; mi++) {
        const int row = m0 + wm * 32 + mi * 16 + (lane >> 2);
        #pragma unroll
        for (int nj = 0; nj < 8; nj++) {
            const int col = n0 + wn * 64 + nj * 8 + (lane & 3) * 2;
            *reinterpret_cast<float2*>(&D[(size_t)row * NL + col]) =
                make_float2(fmaf(acc2[mi][nj][0], inv_lo, acc1[mi][nj][0]),
                            fmaf(acc2[mi][nj][1], inv_lo, acc1[mi][nj][1]));
            *reinterpret_cast<float2*>(&D[(size_t)(row + 8) * NL + col]) =
                make_float2(fmaf(acc2[mi][nj][2], inv_lo, acc1[mi][nj][2]),
                            fmaf(acc2[mi][nj][3], inv_lo, acc1[mi][nj][3]));
        }
    }
}

// ---------------------------------------------------------------------------
// Recurrence + selection: FOUR rows per warp (4 independent shfl chains hide
// SHFL latency; issue-bound). dv carries the 1/512 unscale.
// ---------------------------------------------------------------------------
__device__ __forceinline__ float tree_sum16(const float* a) {
    float t[8];
    #pragma unroll
    for (int j = 0; j < 8; j++) t[j] = a[j] + a[j + 8];
    #pragma unroll
    for (int j = 0; j < 4; j++) t[j] += t[j + 4];
    t[0] += t[2]; t[1] += t[3];
    return t[0] + t[1];
}

__global__ __launch_bounds__(128) void iterate_kernel(
    const float* __restrict__ D, const float* __restrict__ a0,
    float* __restrict__ out, int B, int write_aux)
{
    const int warp0 = (((blockIdx.x * blockDim.x + threadIdx.x) >> 5) << 2);
    const int lane = threadIdx.x & 31;
    if (warp0 >= B) return;

    const float inv_s = 1.0f / A_SCALE;
    float dv[4][16], a[4][16];
    #pragma unroll
    for (int r = 0; r < 4; r++) {
        const size_t ro = (size_t)(warp0 + r) * NL;
        #pragma unroll
        for (int i = 0; i < 16; i++) {
            dv[r][i] = D [ro + lane + 32 * i] * inv_s;
            a[r][i]  = a0[ro + lane + 32 * i];
        }
    }

    const float c1 = 1.0f + KAPPA_C;
    #pragma unroll 1
    for (int t = 0; t < TSTEPS; t++) {
        float p[4];
        #pragma unroll
        for (int r = 0; r < 4; r++) {
            #pragma unroll
            for (int i = 0; i < 16; i++)
                a[r][i] = fmaf(GAMMA_C, a[r][i], dv[r][i]);
            p[r] = tree_sum16(a[r]);
        }
        #pragma unroll
        for (int o = 16; o; o >>= 1) {
            #pragma unroll
            for (int r = 0; r < 4; r++)
                p[r] += __shfl_xor_sync(0xffffffffu, p[r], o);
        }
        #pragma unroll
        for (int r = 0; r < 4; r++) {
            const float kk = -KAPPA_C * p[r];
            #pragma unroll
            for (int i = 0; i < 16; i++)
                a[r][i] = fmaxf(fmaf(c1, a[r][i], kk), 0.f);
        }
    }

    #pragma unroll
    for (int r = 0; r < 4; r++) {
        float s = 0.f, m = -1.f;
        int mi = NL;
        #pragma unroll
        for (int i = 0; i < 16; i++) {
            float v = a[r][i];
            s += v;
            if (v > m) { m = v; mi = lane + 32 * i; }
        }
        #pragma unroll
        for (int o = 16; o; o >>= 1) {
            float om  = __shfl_xor_sync(0xffffffffu, m,  o);
            int   omi = __shfl_xor_sync(0xffffffffu, mi, o);
            float os  = __shfl_xor_sync(0xffffffffu, s,  o);
            s += os;
            if (om > m || (om == m && omi < mi)) { m = om; mi = omi; }
        }
        const size_t ro = (size_t)(warp0 + r) * NL;
        #pragma unroll
        for (int i = 0; i < 16; i++)
            out[ro + lane + 32 * i] = a[r][i];
        if (lane == 0 && write_aux) {
            const size_t base = (size_t)B * NL;
            out[base + warp0 + r]     = (float)mi;
            out[base + B + warp0 + r] = m / fmaxf(s * (1.0f / NL), FLOOR_C);
        }
    }
}

// ---------------------------------------------------------------------------
extern "C" void kernel_launch(void* const* d_in, const int* in_sizes, int n_in,
                              void* d_out, int out_size)
{
    const float* c_lex = (const float*)d_in[0];   // (B, 1024)
    const float* W     = (const float*)d_in[1];   // (512, 1024)
    const float* a0    = (const float*)d_in[2];   // (B, 512)
    float* out = (float*)d_out;

    const int B = in_sizes[0] / NC;               // 4096

    float* drive = nullptr;
    void*  wh = nullptr;
    cudaGetSymbolAddress((void**)&drive, g_drive);
    cudaGetSymbolAddress(&wh, g_Wh);
    const __half* Whi = (const __half*)wh;
    const __half* Wlo = Whi + (size_t)NL * NC;

    // ---- phase 0: W fp32 -> fp16 hi + scaled-lo planes (2 MB, ~1 us) ----
    convert_W_kernel<<<(NL * NC / 8 + 255) / 256, 256>>>(W);

    // ---- phase 1: scaled drive via fp16 HMMA; A converted in-kernel ----
    cudaFuncSetAttribute(gemm_hmma_kernel,
                         cudaFuncAttributeMaxDynamicSharedMemorySize, SMEM_TOT);
    dim3 ggrid(NL / 128, B / 128);   // (4, 32) = 128 CTAs, one wave
    gemm_hmma_kernel<<<ggrid, 256, SMEM_TOT>>>(c_lex, Whi, Wlo, drive);

    // ---- phase 2: 50-step recurrence + selection (4 rows/warp) ----
    const int write_aux = (out_size >= B * NL + 2 * B) ? 1 : 0;
    const int nwarp = B / 4;                       // 1024 warps
    const int nblk = (nwarp * 32 + 127) / 128;     // 256 blocks of 128 thr
    iterate_kernel<<<nblk, 128>>>(drive, a0, out, B, write_aux);
}